// round 15
// baseline (speedup 1.0000x reference)
#include <cuda_runtime.h>
#include <cuda_bf16.h>
#include <math.h>

#define BATCH 64
#define CH    64
#define NPT   256

typedef unsigned long long u64;

// ---------------- global scratch ----------------
__device__ float g_proj[BATCH * 160 * NPT];
__device__ float g_f[BATCH * CH * NPT];            // [b][ch][n] fp32 (residual)
__device__ __nv_bfloat16 g_fh[BATCH * NPT * CH];   // [b][n][ch] hi
__device__ __nv_bfloat16 g_fl[BATCH * NPT * CH];   // [b][n][ch] lo
__device__ __nv_bfloat16 g_hh[BATCH * NPT * 256];  // [b][n][o] hi
__device__ __nv_bfloat16 g_hl[BATCH * NPT * 256];  // [b][n][o] lo
__device__ __nv_bfloat16 g_w1h[256 * 64];
__device__ __nv_bfloat16 g_w1l[256 * 64];
__device__ __nv_bfloat16 g_w2h[64 * 256];
__device__ __nv_bfloat16 g_w2l[64 * 256];

// ---------------- f32x2 helpers ----------------
__device__ __forceinline__ u64 f2pack(float a, float b) {
    u64 r;
    asm("mov.b64 %0, {%1, %2};" : "=l"(r) : "r"(__float_as_uint(a)), "r"(__float_as_uint(b)));
    return r;
}
__device__ __forceinline__ u64 ffma2(u64 a, u64 b, u64 c) {
    u64 d;
    asm("fma.rn.f32x2 %0, %1, %2, %3;" : "=l"(d) : "l"(a), "l"(b), "l"(c));
    return d;
}
__device__ __forceinline__ u64 fadd2(u64 a, u64 b) {
    u64 d;
    asm("add.rn.f32x2 %0, %1, %2;" : "=l"(d) : "l"(a), "l"(b));
    return d;
}
__device__ __forceinline__ void unpack2(u64 v, float& lo, float& hi) {
    unsigned int l, h;
    asm("mov.b64 {%0, %1}, %2;" : "=r"(l), "=r"(h) : "l"(v));
    lo = __uint_as_float(l);
    hi = __uint_as_float(h);
}
__device__ __forceinline__ float hsum2(u64 v) {
    float lo, hi;
    unpack2(v, lo, hi);
    return lo + hi;
}
__device__ __forceinline__ void bn_coef(const float* __restrict__ p, int ch, int cn,
                                        float& sc, float& sh) {
    float ga = __ldg(p + ch);
    float be = __ldg(p + cn + ch);
    float mu = __ldg(p + 2 * cn + ch);
    float va = __ldg(p + 3 * cn + ch);
    sc = ga * rsqrtf(va + 1e-5f);
    sh = fmaf(-mu, sc, be);
}

// mma.sync m16n8k16 bf16: d += a @ b
__device__ __forceinline__ void mma_bf16(float* d, const unsigned int* a, const unsigned int* b) {
    asm volatile("mma.sync.aligned.m16n8k16.row.col.f32.bf16.bf16.f32 "
        "{%0,%1,%2,%3}, {%4,%5,%6,%7}, {%8,%9}, {%0,%1,%2,%3};"
        : "+f"(d[0]), "+f"(d[1]), "+f"(d[2]), "+f"(d[3])
        : "r"(a[0]), "r"(a[1]), "r"(a[2]), "r"(a[3]), "r"(b[0]), "r"(b[1]));
}

// ---------------- kernel 1: projections (unchanged) ----------------
__global__ void proj_kernel(const float* __restrict__ x,
                            const float* __restrict__ ga_q_w, const float* __restrict__ ga_k_w,
                            const float* __restrict__ ga_v_w, const float* __restrict__ ga_lb_w,
                            const float* __restrict__ sa_q_w, const float* __restrict__ sa_k_w,
                            const float* __restrict__ sa_v_w, const float* __restrict__ sa_lb_w) {
    __shared__ float ws[20 * 64];
    int b = blockIdx.x, tid = threadIdx.x;
    int og = blockIdx.y >> 1, nh = blockIdx.y & 1;
    int n = nh * 128 + tid;

    for (int i = tid; i < 1280; i += 128) {
        int r = og * 20 + (i >> 6), c = i & 63;
        float v;
        if      (r < 8)   v = __ldg(&ga_q_w[r * 64 + c]);
        else if (r < 16)  v = __ldg(&ga_k_w[(r - 8) * 64 + c]);
        else if (r < 48)  v = __ldg(&ga_v_w[(r - 16) * 64 + c]);
        else if (r < 56)  v = __ldg(&sa_q_w[(r - 48) * 64 + c]);
        else if (r < 64)  v = __ldg(&sa_k_w[(r - 56) * 64 + c]);
        else if (r < 96)  v = __ldg(&sa_v_w[(r - 64) * 64 + c]);
        else if (r < 128) v = __ldg(&ga_lb_w[(r - 96) * 64 + c]);
        else              v = __ldg(&sa_lb_w[(r - 128) * 64 + c]);
        ws[i] = v;
    }
    __syncthreads();

    u64 xr2[32];
#pragma unroll
    for (int c = 0; c < 32; c++) {
        float a = __ldg(&x[b * 16384 + (2 * c) * 256 + n]);
        float bb = __ldg(&x[b * 16384 + (2 * c + 1) * 256 + n]);
        xr2[c] = f2pack(a, bb);
    }

    float* outp = g_proj + (b * 160 + og * 20) * 256 + n;
#pragma unroll 2
    for (int o = 0; o < 20; o++) {
        const ulonglong2* w2 = (const ulonglong2*)(ws + o * 64);
        u64 a0 = 0ULL, a1 = 0ULL;
#pragma unroll
        for (int i = 0; i < 16; i++) {
            ulonglong2 wv = w2[i];
            a0 = ffma2(wv.x, xr2[2 * i], a0);
            a1 = ffma2(wv.y, xr2[2 * i + 1], a1);
        }
        outp[o * 256] = hsum2(fadd2(a0, a1));
    }
}

// ---------------- kernel 2: attention (+ bf16 f emission) ----------------
#define KS_OFF  0
#define VS_OFF  2048
#define MB_OFF  11264
#define MX_OFF  15616
#define EB_OFF  15872
#define STK_OFF 16128
#define ATTN_SMEM_BYTES (16384 * 4)

__global__ void attn_kernel(const int* __restrict__ stroke_idx,
                            const float* __restrict__ ga_v_b, const float* __restrict__ sa_v_b,
                            const float* __restrict__ ga_bn_p, const float* __restrict__ ga_lb_bn_p,
                            const float* __restrict__ sa_bn_p, const float* __restrict__ sa_lb_bn_p) {
    extern __shared__ float sm[];
    float* Ks   = sm + KS_OFF;
    float* Vs   = sm + VS_OFF;
    float* MB   = sm + MB_OFF;
    float* MX   = sm + MX_OFF;
    float* EB   = sm + EB_OFF;
    int*   stk  = (int*)(sm + STK_OFF);

    int b = blockIdx.x, tid = threadIdx.x;
    int branch = blockIdx.y >> 1, rh = blockIdx.y & 1;
    int row = tid & 127, mh = tid >> 7;
    int n = rh * 128 + row;
    int m0 = mh * 128;

    int qbase  = branch ? 48 : 0;
    int kbase  = qbase + 8;
    int vbase  = branch ? 64 : 16;
    int lbbase = branch ? 128 : 96;
    int choff  = branch ? 32 : 0;
    const float* vb = branch ? sa_v_b : ga_v_b;
    const float* gp = g_proj + b * 160 * 256;
    const float* bnp  = branch ? sa_bn_p : ga_bn_p;
    const float* bnlb = branch ? sa_lb_bn_p : ga_lb_bn_p;

    for (int i = tid; i < 2048; i += 256) {
        int r = i >> 8, m = i & 255;
        Ks[m * 8 + r] = gp[(kbase + r) * 256 + m];
    }
    for (int i = tid; i < 8192; i += 256) {
        int r = i >> 8, m = i & 255;
        Vs[m * 36 + r] = gp[(vbase + r) * 256 + m] + __ldg(vb + r);
    }
    if (branch)
        for (int i = tid; i < 256; i += 256) stk[i] = stroke_idx[b * 256 + i];
    __syncthreads();

    u64 q2[4];
#pragma unroll
    for (int j = 0; j < 4; j++)
        q2[j] = f2pack(gp[(qbase + 2 * j) * 256 + n], gp[(qbase + 2 * j + 1) * 256 + n]);

    const float INV_GA = 0.35355339059327373f;
    const float ESC    = 3.5355339059327378f;

    float mxl = -1e30f;
#pragma unroll 4
    for (int m = m0; m < m0 + 128; m++) {
        const ulonglong2* k2 = (const ulonglong2*)(Ks + m * 8);
        ulonglong2 ka = k2[0], kb = k2[1];
        u64 d0 = ffma2(q2[0], ka.x, 0ULL);
        d0 = ffma2(q2[1], ka.y, d0);
        d0 = ffma2(q2[2], kb.x, d0);
        d0 = ffma2(q2[3], kb.y, d0);
        mxl = fmaxf(mxl, hsum2(d0));
    }
    MX[tid] = mxl;
    __syncthreads();
    float mx = fmaxf(MX[row], MX[row + 128]);

    u64 o2[16];
#pragma unroll
    for (int v = 0; v < 16; v++) o2[v] = 0ULL;
    u64* mb64 = (u64*)MB;
    float vals[32];
    float rescale = 1.f;

    if (branch == 0) {
        float sum = 0.f;
#pragma unroll 2
        for (int m = m0; m < m0 + 128; m++) {
            const ulonglong2* k2 = (const ulonglong2*)(Ks + m * 8);
            ulonglong2 ka = k2[0], kb = k2[1];
            u64 d0 = ffma2(q2[0], ka.x, 0ULL);
            d0 = ffma2(q2[1], ka.y, d0);
            d0 = ffma2(q2[2], kb.x, d0);
            d0 = ffma2(q2[3], kb.y, d0);
            float e = __expf((hsum2(d0) - mx) * INV_GA);
            sum += e;
            u64 ep = f2pack(e, e);
            const ulonglong2* v2p = (const ulonglong2*)(Vs + m * 36);
#pragma unroll
            for (int g = 0; g < 8; g++) {
                ulonglong2 vv = v2p[g];
                o2[2 * g]     = ffma2(ep, vv.x, o2[2 * g]);
                o2[2 * g + 1] = ffma2(ep, vv.y, o2[2 * g + 1]);
            }
        }
        EB[tid] = sum;
        __syncthreads();
        float sumt = EB[row] + EB[row + 128];
        if (mh == 1) {
#pragma unroll
            for (int j = 0; j < 16; j++) mb64[row * 17 + j] = o2[j];
        }
        __syncthreads();
        rescale = 1.f / sumt;
    } else {
        const float CC  = 1.00001000005f;
        const float CM1 = 1.00000500002e-05f;
#pragma unroll
        for (int s = 0; s < 16; s++) MB[s * 256 + tid] = 0.f;
        __syncthreads();
        float E = 0.f;
#pragma unroll 2
        for (int m = m0; m < m0 + 128; m++) {
            const ulonglong2* k2 = (const ulonglong2*)(Ks + m * 8);
            ulonglong2 ka = k2[0], kb = k2[1];
            u64 d0 = ffma2(q2[0], ka.x, 0ULL);
            d0 = ffma2(q2[1], ka.y, d0);
            d0 = ffma2(q2[2], kb.x, d0);
            d0 = ffma2(q2[3], kb.y, d0);
            float e = __expf((hsum2(d0) - mx) * ESC);
            E += e;
            MB[stk[m] * 256 + tid] += e;
        }
        EB[tid] = E;
        __syncthreads();
        if (mh == 0) {
            float Et = EB[row] + EB[row + 128];
            float zi[16];
            float Sinv = 0.f;
#pragma unroll
            for (int s = 0; s < 16; s++) {
                float bsum = MB[s * 256 + row] + MB[s * 256 + row + 128];
                float z = fmaf(-CM1, bsum, CC * Et);
                zi[s] = 1.f / z;
                Sinv += zi[s];
            }
#pragma unroll
            for (int s = 0; s < 16; s++)
                MB[s * 256 + row] = fmaf(-CM1, zi[s], CC * Sinv);
        }
        __syncthreads();
#pragma unroll 2
        for (int m = m0; m < m0 + 128; m++) {
            const ulonglong2* k2 = (const ulonglong2*)(Ks + m * 8);
            ulonglong2 ka = k2[0], kb = k2[1];
            u64 d0 = ffma2(q2[0], ka.x, 0ULL);
            d0 = ffma2(q2[1], ka.y, d0);
            d0 = ffma2(q2[2], kb.x, d0);
            d0 = ffma2(q2[3], kb.y, d0);
            float e = __expf((hsum2(d0) - mx) * ESC);
            float w = e * MB[stk[m] * 256 + row];
            u64 wp = f2pack(w, w);
            const ulonglong2* v2p = (const ulonglong2*)(Vs + m * 36);
#pragma unroll
            for (int g = 0; g < 8; g++) {
                ulonglong2 vv = v2p[g];
                o2[2 * g]     = ffma2(wp, vv.x, o2[2 * g]);
                o2[2 * g + 1] = ffma2(wp, vv.y, o2[2 * g + 1]);
            }
        }
        __syncthreads();
        if (mh == 1) {
#pragma unroll
            for (int j = 0; j < 16; j++) mb64[row * 17 + j] = o2[j];
        }
        __syncthreads();
    }

    if (mh == 0) {
#pragma unroll
        for (int g = 0; g < 16; g++) {
            o2[g] = fadd2(o2[g], mb64[row * 17 + g]);
            float v0, v1;
            unpack2(o2[g], v0, v1);
            int c0 = 2 * g;
            float sc1, sh1, sc2, sh2;
            bn_coef(bnp, c0, 32, sc1, sh1);
            bn_coef(bnlb, c0, 32, sc2, sh2);
            float lb0 = gp[(lbbase + c0) * 256 + n];
            vals[c0] = fmaf(v0 * rescale, sc1, sh1) + fmaf(lb0, sc2, sh2);
            bn_coef(bnp, c0 + 1, 32, sc1, sh1);
            bn_coef(bnlb, c0 + 1, 32, sc2, sh2);
            float lb1 = gp[(lbbase + c0 + 1) * 256 + n];
            vals[c0 + 1] = fmaf(v1 * rescale, sc1, sh1) + fmaf(lb1, sc2, sh2);
        }
        // fp32 g_f for residual
#pragma unroll
        for (int c = 0; c < 32; c++)
            g_f[b * 16384 + (choff + c) * 256 + n] = vals[c];
        // bf16 hi/lo [n][ch] for mlp1 mma
        unsigned int hw[16], lw[16];
#pragma unroll
        for (int j = 0; j < 16; j++) {
            float v0 = vals[2 * j], v1 = vals[2 * j + 1];
            __nv_bfloat16 h0 = __float2bfloat16(v0), h1 = __float2bfloat16(v1);
            __nv_bfloat16 l0 = __float2bfloat16(v0 - __bfloat162float(h0));
            __nv_bfloat16 l1 = __float2bfloat16(v1 - __bfloat162float(h1));
            hw[j] = (unsigned int)__bfloat16_as_ushort(h0) | ((unsigned int)__bfloat16_as_ushort(h1) << 16);
            lw[j] = (unsigned int)__bfloat16_as_ushort(l0) | ((unsigned int)__bfloat16_as_ushort(l1) << 16);
        }
        unsigned int* dh = (unsigned int*)(g_fh + (size_t)b * 16384 + n * 64 + choff);
        unsigned int* dl = (unsigned int*)(g_fl + (size_t)b * 16384 + n * 64 + choff);
        *(uint4*)(dh)      = make_uint4(hw[0], hw[1], hw[2], hw[3]);
        *(uint4*)(dh + 4)  = make_uint4(hw[4], hw[5], hw[6], hw[7]);
        *(uint4*)(dh + 8)  = make_uint4(hw[8], hw[9], hw[10], hw[11]);
        *(uint4*)(dh + 12) = make_uint4(hw[12], hw[13], hw[14], hw[15]);
        *(uint4*)(dl)      = make_uint4(lw[0], lw[1], lw[2], lw[3]);
        *(uint4*)(dl + 4)  = make_uint4(lw[4], lw[5], lw[6], lw[7]);
        *(uint4*)(dl + 8)  = make_uint4(lw[8], lw[9], lw[10], lw[11]);
        *(uint4*)(dl + 12) = make_uint4(lw[12], lw[13], lw[14], lw[15]);
    }
}

// ---------------- weight splits (tiny) ----------------
__global__ void wsplit_kernel(const float* __restrict__ w1, const float* __restrict__ w2) {
    int bx = blockIdx.x;
    const float* src = (bx < 8) ? w2 : w1;
    __nv_bfloat16* dh = (bx < 8) ? g_w2h : g_w1h;
    __nv_bfloat16* dl = (bx < 8) ? g_w2l : g_w1l;
    int i = (bx & 7) * 2048 + threadIdx.x;
#pragma unroll
    for (int j = 0; j < 8; j++, i += 256) {
        float v = __ldg(&src[i]);
        __nv_bfloat16 h = __float2bfloat16(v);
        dh[i] = h;
        dl[i] = __float2bfloat16(v - __bfloat162float(h));
    }
}

// ---------------- kernel 3a: MLP stage 1 via mma.sync ----------------
// grid (16, 64): bx>>2 = o chunk (64 of 256), bx&3 = n chunk (64). block 128 = 4 warps.
// Warp tile 32o x 32n, K=64, 3 hi/lo terms. Writes g_hh/g_hl [n][o] with bn1+relu.
__global__ void mlp1_mma_kernel(const float* __restrict__ bn1) {
    __shared__ float scs[64], shs[64];
    int tid = threadIdx.x;
    int b = blockIdx.y;
    int o0blk = (blockIdx.x >> 2) * 64;
    if (tid < 64) {
        float sc, sh;
        bn_coef(bn1, o0blk + tid, 256, sc, sh);
        scs[tid] = sc;
        shs[tid] = sh;
    }
    __syncthreads();

    int w = tid >> 5, lane = tid & 31;
    int g = lane >> 2, tg = lane & 3;
    int cbase = o0blk + (w & 1) * 32;
    int nbase = (blockIdx.x & 3) * 64 + (w >> 1) * 32;

    const __nv_bfloat16* fh = g_fh + (size_t)b * 16384;
    const __nv_bfloat16* fl = g_fl + (size_t)b * 16384;

    float d[2][4][4];
#pragma unroll
    for (int cs = 0; cs < 2; cs++)
#pragma unroll
        for (int ns = 0; ns < 4; ns++)
#pragma unroll
            for (int j = 0; j < 4; j++) d[cs][ns][j] = 0.f;

#pragma unroll
    for (int k0 = 0; k0 < 64; k0 += 16) {
        unsigned int ah[2][4], al[2][4], bh[4][2], bl[4][2];
#pragma unroll
        for (int cs = 0; cs < 2; cs++) {
            int r0 = (cbase + cs * 16 + g) * 64 + k0 + 2 * tg;
            int r1 = r0 + 8 * 64;
            ah[cs][0] = __ldg((const unsigned int*)(g_w1h + r0));
            ah[cs][1] = __ldg((const unsigned int*)(g_w1h + r1));
            ah[cs][2] = __ldg((const unsigned int*)(g_w1h + r0 + 8));
            ah[cs][3] = __ldg((const unsigned int*)(g_w1h + r1 + 8));
            al[cs][0] = __ldg((const unsigned int*)(g_w1l + r0));
            al[cs][1] = __ldg((const unsigned int*)(g_w1l + r1));
            al[cs][2] = __ldg((const unsigned int*)(g_w1l + r0 + 8));
            al[cs][3] = __ldg((const unsigned int*)(g_w1l + r1 + 8));
        }
#pragma unroll
        for (int ns = 0; ns < 4; ns++) {
            int rb = (nbase + ns * 8 + g) * 64 + k0 + 2 * tg;
            bh[ns][0] = __ldg((const unsigned int*)(fh + rb));
            bh[ns][1] = __ldg((const unsigned int*)(fh + rb + 8));
            bl[ns][0] = __ldg((const unsigned int*)(fl + rb));
            bl[ns][1] = __ldg((const unsigned int*)(fl + rb + 8));
        }
#pragma unroll
        for (int cs = 0; cs < 2; cs++)
#pragma unroll
            for (int ns = 0; ns < 4; ns++) {
                mma_bf16(d[cs][ns], ah[cs], bh[ns]);
                mma_bf16(d[cs][ns], al[cs], bh[ns]);
                mma_bf16(d[cs][ns], ah[cs], bl[ns]);
            }
    }

    // epilogue: bn1 + relu + hi/lo split, write g_hh/g_hl [n][o]
    __nv_bfloat16* hhp = g_hh + (size_t)b * 65536;
    __nv_bfloat16* hlp = g_hl + (size_t)b * 65536;
#pragma unroll
    for (int cs = 0; cs < 2; cs++) {
        int o0 = cbase + cs * 16 + g;
        int o1 = o0 + 8;
        float sc0 = scs[o0 - o0blk], sh0 = shs[o0 - o0blk];
        float sc1 = scs[o1 - o0blk], sh1 = shs[o1 - o0blk];
#pragma unroll
        for (int ns = 0; ns < 4; ns++) {
            int n = nbase + ns * 8 + 2 * tg;
            const float* dd = d[cs][ns];
            float v00 = fmaxf(fmaf(dd[0], sc0, sh0), 0.f);   // (o0, n)
            float v01 = fmaxf(fmaf(dd[1], sc0, sh0), 0.f);   // (o0, n+1)
            float v10 = fmaxf(fmaf(dd[2], sc1, sh1), 0.f);   // (o1, n)
            float v11 = fmaxf(fmaf(dd[3], sc1, sh1), 0.f);   // (o1, n+1)
            __nv_bfloat16 h00 = __float2bfloat16(v00), h01 = __float2bfloat16(v01);
            __nv_bfloat16 h10 = __float2bfloat16(v10), h11 = __float2bfloat16(v11);
            hhp[n * 256 + o0]       = h00;
            hhp[(n + 1) * 256 + o0] = h01;
            hhp[n * 256 + o1]       = h10;
            hhp[(n + 1) * 256 + o1] = h11;
            hlp[n * 256 + o0]       = __float2bfloat16(v00 - __bfloat162float(h00));
            hlp[(n + 1) * 256 + o0] = __float2bfloat16(v01 - __bfloat162float(h01));
            hlp[n * 256 + o1]       = __float2bfloat16(v10 - __bfloat162float(h10));
            hlp[(n + 1) * 256 + o1] = __float2bfloat16(v11 - __bfloat162float(h11));
        }
    }
}

// ---------------- kernel 3b: MLP stage 2 via mma.sync (unchanged) ----------------
// grid (4, 64): bx = n chunk (64). block 128 = 4 warps; warp tile 32ch x 32n.
__global__ void mlp2_mma_kernel(const float* __restrict__ bn2, float* __restrict__ out) {
    __shared__ float scs[64], shs[64];
    int tid = threadIdx.x;
    int b = blockIdx.y;
    if (tid < 64) {
        float sc, sh;
        bn_coef(bn2, tid, 64, sc, sh);
        scs[tid] = sc;
        shs[tid] = sh;
    }
    __syncthreads();

    int w = tid >> 5, lane = tid & 31;
    int g = lane >> 2, tg = lane & 3;
    int cbase = (w & 1) * 32;
    int nbase = blockIdx.x * 64 + (w >> 1) * 32;

    const __nv_bfloat16* hh = g_hh + (size_t)b * 65536;
    const __nv_bfloat16* hl = g_hl + (size_t)b * 65536;

    float d[2][4][4];
#pragma unroll
    for (int cs = 0; cs < 2; cs++)
#pragma unroll
        for (int ns = 0; ns < 4; ns++)
#pragma unroll
            for (int j = 0; j < 4; j++) d[cs][ns][j] = 0.f;

    for (int k0 = 0; k0 < 256; k0 += 16) {
        unsigned int ah[2][4], al[2][4], bh[4][2], bl[4][2];
#pragma unroll
        for (int cs = 0; cs < 2; cs++) {
            int r0 = (cbase + cs * 16 + g) * 256 + k0 + 2 * tg;
            int r1 = r0 + 8 * 256;
            ah[cs][0] = __ldg((const unsigned int*)(g_w2h + r0));
            ah[cs][1] = __ldg((const unsigned int*)(g_w2h + r1));
            ah[cs][2] = __ldg((const unsigned int*)(g_w2h + r0 + 8));
            ah[cs][3] = __ldg((const unsigned int*)(g_w2h + r1 + 8));
            al[cs][0] = __ldg((const unsigned int*)(g_w2l + r0));
            al[cs][1] = __ldg((const unsigned int*)(g_w2l + r1));
            al[cs][2] = __ldg((const unsigned int*)(g_w2l + r0 + 8));
            al[cs][3] = __ldg((const unsigned int*)(g_w2l + r1 + 8));
        }
#pragma unroll
        for (int ns = 0; ns < 4; ns++) {
            int rb = (nbase + ns * 8 + g) * 256 + k0 + 2 * tg;
            bh[ns][0] = __ldg((const unsigned int*)(hh + rb));
            bh[ns][1] = __ldg((const unsigned int*)(hh + rb + 8));
            bl[ns][0] = __ldg((const unsigned int*)(hl + rb));
            bl[ns][1] = __ldg((const unsigned int*)(hl + rb + 8));
        }
#pragma unroll
        for (int cs = 0; cs < 2; cs++)
#pragma unroll
            for (int ns = 0; ns < 4; ns++) {
                mma_bf16(d[cs][ns], ah[cs], bh[ns]);
                mma_bf16(d[cs][ns], al[cs], bh[ns]);
                mma_bf16(d[cs][ns], ah[cs], bl[ns]);
            }
    }

#pragma unroll
    for (int cs = 0; cs < 2; cs++) {
        int c0r = cbase + cs * 16 + g;
        int c1r = c0r + 8;
        float sc0 = scs[c0r], sh0 = shs[c0r];
        float sc1 = scs[c1r], sh1 = shs[c1r];
#pragma unroll
        for (int ns = 0; ns < 4; ns++) {
            int n = nbase + ns * 8 + 2 * tg;
            const float* dd = d[cs][ns];
            float2 f0 = *(const float2*)&g_f[b * 16384 + c0r * 256 + n];
            float2 f1 = *(const float2*)&g_f[b * 16384 + c1r * 256 + n];
            float2 r0, r1;
            r0.x = fmaxf(fmaf(dd[0], sc0, sh0) + f0.x, 0.f);
            r0.y = fmaxf(fmaf(dd[1], sc0, sh0) + f0.y, 0.f);
            r1.x = fmaxf(fmaf(dd[2], sc1, sh1) + f1.x, 0.f);
            r1.y = fmaxf(fmaf(dd[3], sc1, sh1) + f1.y, 0.f);
            *(float2*)&out[b * 16384 + c0r * 256 + n] = r0;
            *(float2*)&out[b * 16384 + c1r * 256 + n] = r1;
        }
    }
}

// ---------------- launch ----------------
extern "C" void kernel_launch(void* const* d_in, const int* in_sizes, int n_in,
                              void* d_out, int out_size) {
    int base = (in_sizes[2] == 512) ? 2 : 3;

    const float* x          = (const float*)d_in[0];
    const int*   stroke     = (const int*)d_in[1];
    const float* ga_q_w     = (const float*)d_in[base + 0];
    const float* ga_k_w     = (const float*)d_in[base + 1];
    const float* ga_v_w     = (const float*)d_in[base + 2];
    const float* ga_v_b     = (const float*)d_in[base + 3];
    const float* ga_bn_p    = (const float*)d_in[base + 4];
    const float* ga_lb_w    = (const float*)d_in[base + 5];
    const float* ga_lb_bn_p = (const float*)d_in[base + 6];
    const float* sa_q_w     = (const float*)d_in[base + 7];
    const float* sa_k_w     = (const float*)d_in[base + 8];
    const float* sa_v_w     = (const float*)d_in[base + 9];
    const float* sa_v_b     = (const float*)d_in[base + 10];
    const float* sa_bn_p    = (const float*)d_in[base + 11];
    const float* sa_lb_w    = (const float*)d_in[base + 12];
    const float* sa_lb_bn_p = (const float*)d_in[base + 13];
    const float* mlp_w1     = (const float*)d_in[base + 14];
    const float* mlp_bn1_p  = (const float*)d_in[base + 15];
    const float* mlp_w2     = (const float*)d_in[base + 16];
    const float* mlp_bn2_p  = (const float*)d_in[base + 17];

    cudaFuncSetAttribute(attn_kernel, cudaFuncAttributeMaxDynamicSharedMemorySize, ATTN_SMEM_BYTES);

    proj_kernel<<<dim3(64, 16), 128>>>(x, ga_q_w, ga_k_w, ga_v_w, ga_lb_w,
                                       sa_q_w, sa_k_w, sa_v_w, sa_lb_w);
    wsplit_kernel<<<16, 256>>>(mlp_w1, mlp_w2);
    attn_kernel<<<dim3(64, 4), 256, ATTN_SMEM_BYTES>>>(stroke, ga_v_b, sa_v_b,
                                                       ga_bn_p, ga_lb_bn_p,
                                                       sa_bn_p, sa_lb_bn_p);
    mlp1_mma_kernel<<<dim3(16, 64), 128>>>(mlp_bn1_p);
    mlp2_mma_kernel<<<dim3(4, 64), 128>>>(mlp_bn2_p, (float*)d_out);
}

// round 16
// speedup vs baseline: 1.0781x; 1.0781x over previous
#include <cuda_runtime.h>
#include <cuda_bf16.h>
#include <math.h>

#define BATCH 64
#define CH    64
#define NPT   256

typedef unsigned long long u64;

// ---------------- global scratch ----------------
// Interleaved hi/lo bf16 format: for even element index e, uint word [e] holds
// bf16x2 hi of elements (e,e+1) and [e+1] holds the lo residual pair.
__device__ float g_proj[BATCH * 160 * NPT];
__device__ float g_f[BATCH * CH * NPT];        // [b][ch][n] fp32 (residual)
__device__ unsigned int g_fhl[BATCH * NPT * 64];    // f  [n][ch] interleaved
__device__ unsigned int g_hhl[BATCH * NPT * 256];   // h  [n][o]  interleaved
__device__ unsigned int g_w1hl[256 * 64];           // w1 [o][k]  interleaved
__device__ unsigned int g_w2hl[64 * 256];           // w2 [c][k]  interleaved

// ---------------- f32x2 helpers ----------------
__device__ __forceinline__ u64 f2pack(float a, float b) {
    u64 r;
    asm("mov.b64 %0, {%1, %2};" : "=l"(r) : "r"(__float_as_uint(a)), "r"(__float_as_uint(b)));
    return r;
}
__device__ __forceinline__ u64 ffma2(u64 a, u64 b, u64 c) {
    u64 d;
    asm("fma.rn.f32x2 %0, %1, %2, %3;" : "=l"(d) : "l"(a), "l"(b), "l"(c));
    return d;
}
__device__ __forceinline__ u64 fadd2(u64 a, u64 b) {
    u64 d;
    asm("add.rn.f32x2 %0, %1, %2;" : "=l"(d) : "l"(a), "l"(b));
    return d;
}
__device__ __forceinline__ void unpack2(u64 v, float& lo, float& hi) {
    unsigned int l, h;
    asm("mov.b64 {%0, %1}, %2;" : "=r"(l), "=r"(h) : "l"(v));
    lo = __uint_as_float(l);
    hi = __uint_as_float(h);
}
__device__ __forceinline__ float hsum2(u64 v) {
    float lo, hi;
    unpack2(v, lo, hi);
    return lo + hi;
}
__device__ __forceinline__ void bn_coef(const float* __restrict__ p, int ch, int cn,
                                        float& sc, float& sh) {
    float ga = __ldg(p + ch);
    float be = __ldg(p + cn + ch);
    float mu = __ldg(p + 2 * cn + ch);
    float va = __ldg(p + 3 * cn + ch);
    sc = ga * rsqrtf(va + 1e-5f);
    sh = fmaf(-mu, sc, be);
}

// mma.sync m16n8k16 bf16: d += a @ b
__device__ __forceinline__ void mma_bf16(float* d, const unsigned int* a, const unsigned int* b) {
    asm volatile("mma.sync.aligned.m16n8k16.row.col.f32.bf16.bf16.f32 "
        "{%0,%1,%2,%3}, {%4,%5,%6,%7}, {%8,%9}, {%0,%1,%2,%3};"
        : "+f"(d[0]), "+f"(d[1]), "+f"(d[2]), "+f"(d[3])
        : "r"(a[0]), "r"(a[1]), "r"(a[2]), "r"(a[3]), "r"(b[0]), "r"(b[1]));
}
__device__ __forceinline__ unsigned int packbf(float v0, float v1, float& r0, float& r1) {
    __nv_bfloat16 h0 = __float2bfloat16(v0), h1 = __float2bfloat16(v1);
    r0 = v0 - __bfloat162float(h0);
    r1 = v1 - __bfloat162float(h1);
    return (unsigned int)__bfloat16_as_ushort(h0) | ((unsigned int)__bfloat16_as_ushort(h1) << 16);
}
__device__ __forceinline__ unsigned int packbf2(float v0, float v1) {
    __nv_bfloat16 h0 = __float2bfloat16(v0), h1 = __float2bfloat16(v1);
    return (unsigned int)__bfloat16_as_ushort(h0) | ((unsigned int)__bfloat16_as_ushort(h1) << 16);
}

// ---------------- kernel 1: projections (unchanged) ----------------
__global__ void proj_kernel(const float* __restrict__ x,
                            const float* __restrict__ ga_q_w, const float* __restrict__ ga_k_w,
                            const float* __restrict__ ga_v_w, const float* __restrict__ ga_lb_w,
                            const float* __restrict__ sa_q_w, const float* __restrict__ sa_k_w,
                            const float* __restrict__ sa_v_w, const float* __restrict__ sa_lb_w) {
    __shared__ float ws[20 * 64];
    int b = blockIdx.x, tid = threadIdx.x;
    int og = blockIdx.y >> 1, nh = blockIdx.y & 1;
    int n = nh * 128 + tid;

    for (int i = tid; i < 1280; i += 128) {
        int r = og * 20 + (i >> 6), c = i & 63;
        float v;
        if      (r < 8)   v = __ldg(&ga_q_w[r * 64 + c]);
        else if (r < 16)  v = __ldg(&ga_k_w[(r - 8) * 64 + c]);
        else if (r < 48)  v = __ldg(&ga_v_w[(r - 16) * 64 + c]);
        else if (r < 56)  v = __ldg(&sa_q_w[(r - 48) * 64 + c]);
        else if (r < 64)  v = __ldg(&sa_k_w[(r - 56) * 64 + c]);
        else if (r < 96)  v = __ldg(&sa_v_w[(r - 64) * 64 + c]);
        else if (r < 128) v = __ldg(&ga_lb_w[(r - 96) * 64 + c]);
        else              v = __ldg(&sa_lb_w[(r - 128) * 64 + c]);
        ws[i] = v;
    }
    __syncthreads();

    u64 xr2[32];
#pragma unroll
    for (int c = 0; c < 32; c++) {
        float a = __ldg(&x[b * 16384 + (2 * c) * 256 + n]);
        float bb = __ldg(&x[b * 16384 + (2 * c + 1) * 256 + n]);
        xr2[c] = f2pack(a, bb);
    }

    float* outp = g_proj + (b * 160 + og * 20) * 256 + n;
#pragma unroll 2
    for (int o = 0; o < 20; o++) {
        const ulonglong2* w2 = (const ulonglong2*)(ws + o * 64);
        u64 a0 = 0ULL, a1 = 0ULL;
#pragma unroll
        for (int i = 0; i < 16; i++) {
            ulonglong2 wv = w2[i];
            a0 = ffma2(wv.x, xr2[2 * i], a0);
            a1 = ffma2(wv.y, xr2[2 * i + 1], a1);
        }
        outp[o * 256] = hsum2(fadd2(a0, a1));
    }
}

// ---------------- kernel 2: attention (+ interleaved bf16 f emission) ----------------
#define KS_OFF  0
#define VS_OFF  2048
#define MB_OFF  11264
#define MX_OFF  15616
#define EB_OFF  15872
#define STK_OFF 16128
#define ATTN_SMEM_BYTES (16384 * 4)

__global__ void attn_kernel(const int* __restrict__ stroke_idx,
                            const float* __restrict__ ga_v_b, const float* __restrict__ sa_v_b,
                            const float* __restrict__ ga_bn_p, const float* __restrict__ ga_lb_bn_p,
                            const float* __restrict__ sa_bn_p, const float* __restrict__ sa_lb_bn_p) {
    extern __shared__ float sm[];
    float* Ks   = sm + KS_OFF;
    float* Vs   = sm + VS_OFF;
    float* MB   = sm + MB_OFF;
    float* MX   = sm + MX_OFF;
    float* EB   = sm + EB_OFF;
    int*   stk  = (int*)(sm + STK_OFF);

    int b = blockIdx.x, tid = threadIdx.x;
    int branch = blockIdx.y >> 1, rh = blockIdx.y & 1;
    int row = tid & 127, mh = tid >> 7;
    int n = rh * 128 + row;
    int m0 = mh * 128;

    int qbase  = branch ? 48 : 0;
    int kbase  = qbase + 8;
    int vbase  = branch ? 64 : 16;
    int lbbase = branch ? 128 : 96;
    int choff  = branch ? 32 : 0;
    const float* vb = branch ? sa_v_b : ga_v_b;
    const float* gp = g_proj + b * 160 * 256;
    const float* bnp  = branch ? sa_bn_p : ga_bn_p;
    const float* bnlb = branch ? sa_lb_bn_p : ga_lb_bn_p;

    for (int i = tid; i < 2048; i += 256) {
        int r = i >> 8, m = i & 255;
        Ks[m * 8 + r] = gp[(kbase + r) * 256 + m];
    }
    for (int i = tid; i < 8192; i += 256) {
        int r = i >> 8, m = i & 255;
        Vs[m * 36 + r] = gp[(vbase + r) * 256 + m] + __ldg(vb + r);
    }
    if (branch)
        for (int i = tid; i < 256; i += 256) stk[i] = stroke_idx[b * 256 + i];
    __syncthreads();

    u64 q2[4];
#pragma unroll
    for (int j = 0; j < 4; j++)
        q2[j] = f2pack(gp[(qbase + 2 * j) * 256 + n], gp[(qbase + 2 * j + 1) * 256 + n]);

    const float INV_GA = 0.35355339059327373f;
    const float ESC    = 3.5355339059327378f;

    float mxl = -1e30f;
#pragma unroll 4
    for (int m = m0; m < m0 + 128; m++) {
        const ulonglong2* k2 = (const ulonglong2*)(Ks + m * 8);
        ulonglong2 ka = k2[0], kb = k2[1];
        u64 d0 = ffma2(q2[0], ka.x, 0ULL);
        d0 = ffma2(q2[1], ka.y, d0);
        d0 = ffma2(q2[2], kb.x, d0);
        d0 = ffma2(q2[3], kb.y, d0);
        mxl = fmaxf(mxl, hsum2(d0));
    }
    MX[tid] = mxl;
    __syncthreads();
    float mx = fmaxf(MX[row], MX[row + 128]);

    u64 o2[16];
#pragma unroll
    for (int v = 0; v < 16; v++) o2[v] = 0ULL;
    u64* mb64 = (u64*)MB;
    float vals[32];
    float rescale = 1.f;

    if (branch == 0) {
        float sum = 0.f;
#pragma unroll 2
        for (int m = m0; m < m0 + 128; m++) {
            const ulonglong2* k2 = (const ulonglong2*)(Ks + m * 8);
            ulonglong2 ka = k2[0], kb = k2[1];
            u64 d0 = ffma2(q2[0], ka.x, 0ULL);
            d0 = ffma2(q2[1], ka.y, d0);
            d0 = ffma2(q2[2], kb.x, d0);
            d0 = ffma2(q2[3], kb.y, d0);
            float e = __expf((hsum2(d0) - mx) * INV_GA);
            sum += e;
            u64 ep = f2pack(e, e);
            const ulonglong2* v2p = (const ulonglong2*)(Vs + m * 36);
#pragma unroll
            for (int g = 0; g < 8; g++) {
                ulonglong2 vv = v2p[g];
                o2[2 * g]     = ffma2(ep, vv.x, o2[2 * g]);
                o2[2 * g + 1] = ffma2(ep, vv.y, o2[2 * g + 1]);
            }
        }
        EB[tid] = sum;
        __syncthreads();
        float sumt = EB[row] + EB[row + 128];
        if (mh == 1) {
#pragma unroll
            for (int j = 0; j < 16; j++) mb64[row * 17 + j] = o2[j];
        }
        __syncthreads();
        rescale = 1.f / sumt;
    } else {
        const float CC  = 1.00001000005f;
        const float CM1 = 1.00000500002e-05f;
#pragma unroll
        for (int s = 0; s < 16; s++) MB[s * 256 + tid] = 0.f;
        __syncthreads();
        float E = 0.f;
#pragma unroll 2
        for (int m = m0; m < m0 + 128; m++) {
            const ulonglong2* k2 = (const ulonglong2*)(Ks + m * 8);
            ulonglong2 ka = k2[0], kb = k2[1];
            u64 d0 = ffma2(q2[0], ka.x, 0ULL);
            d0 = ffma2(q2[1], ka.y, d0);
            d0 = ffma2(q2[2], kb.x, d0);
            d0 = ffma2(q2[3], kb.y, d0);
            float e = __expf((hsum2(d0) - mx) * ESC);
            E += e;
            MB[stk[m] * 256 + tid] += e;
        }
        EB[tid] = E;
        __syncthreads();
        if (mh == 0) {
            float Et = EB[row] + EB[row + 128];
            float zi[16];
            float Sinv = 0.f;
#pragma unroll
            for (int s = 0; s < 16; s++) {
                float bsum = MB[s * 256 + row] + MB[s * 256 + row + 128];
                float z = fmaf(-CM1, bsum, CC * Et);
                zi[s] = 1.f / z;
                Sinv += zi[s];
            }
#pragma unroll
            for (int s = 0; s < 16; s++)
                MB[s * 256 + row] = fmaf(-CM1, zi[s], CC * Sinv);
        }
        __syncthreads();
#pragma unroll 2
        for (int m = m0; m < m0 + 128; m++) {
            const ulonglong2* k2 = (const ulonglong2*)(Ks + m * 8);
            ulonglong2 ka = k2[0], kb = k2[1];
            u64 d0 = ffma2(q2[0], ka.x, 0ULL);
            d0 = ffma2(q2[1], ka.y, d0);
            d0 = ffma2(q2[2], kb.x, d0);
            d0 = ffma2(q2[3], kb.y, d0);
            float e = __expf((hsum2(d0) - mx) * ESC);
            float w = e * MB[stk[m] * 256 + row];
            u64 wp = f2pack(w, w);
            const ulonglong2* v2p = (const ulonglong2*)(Vs + m * 36);
#pragma unroll
            for (int g = 0; g < 8; g++) {
                ulonglong2 vv = v2p[g];
                o2[2 * g]     = ffma2(wp, vv.x, o2[2 * g]);
                o2[2 * g + 1] = ffma2(wp, vv.y, o2[2 * g + 1]);
            }
        }
        __syncthreads();
        if (mh == 1) {
#pragma unroll
            for (int j = 0; j < 16; j++) mb64[row * 17 + j] = o2[j];
        }
        __syncthreads();
    }

    if (mh == 0) {
#pragma unroll
        for (int g = 0; g < 16; g++) {
            o2[g] = fadd2(o2[g], mb64[row * 17 + g]);
            float v0, v1;
            unpack2(o2[g], v0, v1);
            int c0 = 2 * g;
            float sc1, sh1, sc2, sh2;
            bn_coef(bnp, c0, 32, sc1, sh1);
            bn_coef(bnlb, c0, 32, sc2, sh2);
            float lb0 = gp[(lbbase + c0) * 256 + n];
            vals[c0] = fmaf(v0 * rescale, sc1, sh1) + fmaf(lb0, sc2, sh2);
            bn_coef(bnp, c0 + 1, 32, sc1, sh1);
            bn_coef(bnlb, c0 + 1, 32, sc2, sh2);
            float lb1 = gp[(lbbase + c0 + 1) * 256 + n];
            vals[c0 + 1] = fmaf(v1 * rescale, sc1, sh1) + fmaf(lb1, sc2, sh2);
        }
        // fp32 g_f for residual
#pragma unroll
        for (int c = 0; c < 32; c++)
            g_f[b * 16384 + (choff + c) * 256 + n] = vals[c];
        // interleaved hi/lo bf16 [n][ch]
        unsigned int iw[32];
#pragma unroll
        for (int j = 0; j < 16; j++) {
            float r0, r1;
            iw[2 * j] = packbf(vals[2 * j], vals[2 * j + 1], r0, r1);
            iw[2 * j + 1] = packbf2(r0, r1);
        }
        unsigned int* dst = g_fhl + (size_t)b * 16384 + n * 64 + choff;
#pragma unroll
        for (int q = 0; q < 8; q++)
            *(uint4*)(dst + 4 * q) = make_uint4(iw[4 * q], iw[4 * q + 1], iw[4 * q + 2], iw[4 * q + 3]);
    }
}

// ---------------- weight splits (interleaved) ----------------
__global__ void wsplit_kernel(const float* __restrict__ w1, const float* __restrict__ w2) {
    int bx = blockIdx.x;
    const float* src = (bx < 8) ? w2 : w1;
    unsigned int* dst = (bx < 8) ? g_w2hl : g_w1hl;
    int e = (bx & 7) * 2048 + threadIdx.x * 2;     // even element index
#pragma unroll
    for (int j = 0; j < 4; j++, e += 512) {
        float v0 = __ldg(&src[e]), v1 = __ldg(&src[e + 1]);
        float r0, r1;
        unsigned int hi = packbf(v0, v1, r0, r1);
        *(uint2*)(dst + e) = make_uint2(hi, packbf2(r0, r1));
    }
}

// ---------------- kernel 3a: MLP stage 1 via mma.sync (interleaved loads) ----------------
// grid (16, 64): bx>>2 = o chunk (64 of 256), bx&3 = n chunk (64). block 128 = 4 warps.
__global__ void mlp1_mma_kernel(const float* __restrict__ bn1) {
    __shared__ float scs[64], shs[64];
    int tid = threadIdx.x;
    int b = blockIdx.y;
    int o0blk = (blockIdx.x >> 2) * 64;
    if (tid < 64) {
        float sc, sh;
        bn_coef(bn1, o0blk + tid, 256, sc, sh);
        scs[tid] = sc;
        shs[tid] = sh;
    }
    __syncthreads();

    int w = tid >> 5, lane = tid & 31;
    int g = lane >> 2, tg = lane & 3;
    int cbase = o0blk + (w & 1) * 32;
    int nbase = (blockIdx.x & 3) * 64 + (w >> 1) * 32;

    const unsigned int* fp = g_fhl + (size_t)b * 16384;

    float d[2][4][4];
#pragma unroll
    for (int cs = 0; cs < 2; cs++)
#pragma unroll
        for (int ns = 0; ns < 4; ns++)
#pragma unroll
            for (int j = 0; j < 4; j++) d[cs][ns][j] = 0.f;

#pragma unroll
    for (int k0 = 0; k0 < 64; k0 += 16) {
        unsigned int ah[2][4], al[2][4], bh[4][2], bl[4][2];
#pragma unroll
        for (int cs = 0; cs < 2; cs++) {
            int r0 = (cbase + cs * 16 + g) * 64 + k0 + 2 * tg;
            int r1 = r0 + 8 * 64;
            uint2 v0 = *(const uint2*)(g_w1hl + r0);
            uint2 v1 = *(const uint2*)(g_w1hl + r1);
            uint2 v2 = *(const uint2*)(g_w1hl + r0 + 8);
            uint2 v3 = *(const uint2*)(g_w1hl + r1 + 8);
            ah[cs][0] = v0.x; al[cs][0] = v0.y;
            ah[cs][1] = v1.x; al[cs][1] = v1.y;
            ah[cs][2] = v2.x; al[cs][2] = v2.y;
            ah[cs][3] = v3.x; al[cs][3] = v3.y;
        }
#pragma unroll
        for (int ns = 0; ns < 4; ns++) {
            int rb = (nbase + ns * 8 + g) * 64 + k0 + 2 * tg;
            uint2 v0 = *(const uint2*)(fp + rb);
            uint2 v1 = *(const uint2*)(fp + rb + 8);
            bh[ns][0] = v0.x; bl[ns][0] = v0.y;
            bh[ns][1] = v1.x; bl[ns][1] = v1.y;
        }
#pragma unroll
        for (int cs = 0; cs < 2; cs++)
#pragma unroll
            for (int ns = 0; ns < 4; ns++) {
                mma_bf16(d[cs][ns], ah[cs], bh[ns]);
                mma_bf16(d[cs][ns], al[cs], bh[ns]);
                mma_bf16(d[cs][ns], ah[cs], bl[ns]);
            }
    }

    // epilogue: bn1 + relu + hi/lo split -> interleaved g_hhl [n][o]
    unsigned short* hp = (unsigned short*)(g_hhl + (size_t)b * 65536);
#pragma unroll
    for (int cs = 0; cs < 2; cs++) {
        int o0 = cbase + cs * 16 + g;
        int o1 = o0 + 8;
        float sc0 = scs[o0 - o0blk], sh0 = shs[o0 - o0blk];
        float sc1 = scs[o1 - o0blk], sh1 = shs[o1 - o0blk];
#pragma unroll
        for (int ns = 0; ns < 4; ns++) {
            int n = nbase + ns * 8 + 2 * tg;
            const float* dd = d[cs][ns];
            float v00 = fmaxf(fmaf(dd[0], sc0, sh0), 0.f);   // (o0, n)
            float v01 = fmaxf(fmaf(dd[1], sc0, sh0), 0.f);   // (o0, n+1)
            float v10 = fmaxf(fmaf(dd[2], sc1, sh1), 0.f);   // (o1, n)
            float v11 = fmaxf(fmaf(dd[3], sc1, sh1), 0.f);   // (o1, n+1)
            __nv_bfloat16 h00 = __float2bfloat16(v00), h01 = __float2bfloat16(v01);
            __nv_bfloat16 h10 = __float2bfloat16(v10), h11 = __float2bfloat16(v11);
            int e00 = n * 256 + o0, e01 = (n + 1) * 256 + o0;
            int e10 = n * 256 + o1, e11 = (n + 1) * 256 + o1;
            hp[4 * (e00 >> 1) + (e00 & 1)] = __bfloat16_as_ushort(h00);
            hp[4 * (e01 >> 1) + (e01 & 1)] = __bfloat16_as_ushort(h01);
            hp[4 * (e10 >> 1) + (e10 & 1)] = __bfloat16_as_ushort(h10);
            hp[4 * (e11 >> 1) + (e11 & 1)] = __bfloat16_as_ushort(h11);
            hp[4 * (e00 >> 1) + 2 + (e00 & 1)] = __bfloat16_as_ushort(__float2bfloat16(v00 - __bfloat162float(h00)));
            hp[4 * (e01 >> 1) + 2 + (e01 & 1)] = __bfloat16_as_ushort(__float2bfloat16(v01 - __bfloat162float(h01)));
            hp[4 * (e10 >> 1) + 2 + (e10 & 1)] = __bfloat16_as_ushort(__float2bfloat16(v10 - __bfloat162float(h10)));
            hp[4 * (e11 >> 1) + 2 + (e11 & 1)] = __bfloat16_as_ushort(__float2bfloat16(v11 - __bfloat162float(h11)));
        }
    }
}

// ---------------- kernel 3b: MLP stage 2 via mma.sync (interleaved loads) ----------------
// grid (4, 64): bx = n chunk (64). block 128 = 4 warps; warp tile 32ch x 32n.
__global__ void mlp2_mma_kernel(const float* __restrict__ bn2, float* __restrict__ out) {
    __shared__ float scs[64], shs[64];
    int tid = threadIdx.x;
    int b = blockIdx.y;
    if (tid < 64) {
        float sc, sh;
        bn_coef(bn2, tid, 64, sc, sh);
        scs[tid] = sc;
        shs[tid] = sh;
    }
    __syncthreads();

    int w = tid >> 5, lane = tid & 31;
    int g = lane >> 2, tg = lane & 3;
    int cbase = (w & 1) * 32;
    int nbase = blockIdx.x * 64 + (w >> 1) * 32;

    const unsigned int* hp = g_hhl + (size_t)b * 65536;

    float d[2][4][4];
#pragma unroll
    for (int cs = 0; cs < 2; cs++)
#pragma unroll
        for (int ns = 0; ns < 4; ns++)
#pragma unroll
            for (int j = 0; j < 4; j++) d[cs][ns][j] = 0.f;

    for (int k0 = 0; k0 < 256; k0 += 16) {
        unsigned int ah[2][4], al[2][4], bh[4][2], bl[4][2];
#pragma unroll
        for (int cs = 0; cs < 2; cs++) {
            int r0 = (cbase + cs * 16 + g) * 256 + k0 + 2 * tg;
            int r1 = r0 + 8 * 256;
            uint2 v0 = *(const uint2*)(g_w2hl + r0);
            uint2 v1 = *(const uint2*)(g_w2hl + r1);
            uint2 v2 = *(const uint2*)(g_w2hl + r0 + 8);
            uint2 v3 = *(const uint2*)(g_w2hl + r1 + 8);
            ah[cs][0] = v0.x; al[cs][0] = v0.y;
            ah[cs][1] = v1.x; al[cs][1] = v1.y;
            ah[cs][2] = v2.x; al[cs][2] = v2.y;
            ah[cs][3] = v3.x; al[cs][3] = v3.y;
        }
#pragma unroll
        for (int ns = 0; ns < 4; ns++) {
            int rb = (nbase + ns * 8 + g) * 256 + k0 + 2 * tg;
            uint2 v0 = *(const uint2*)(hp + rb);
            uint2 v1 = *(const uint2*)(hp + rb + 8);
            bh[ns][0] = v0.x; bl[ns][0] = v0.y;
            bh[ns][1] = v1.x; bl[ns][1] = v1.y;
        }
#pragma unroll
        for (int cs = 0; cs < 2; cs++)
#pragma unroll
            for (int ns = 0; ns < 4; ns++) {
                mma_bf16(d[cs][ns], ah[cs], bh[ns]);
                mma_bf16(d[cs][ns], al[cs], bh[ns]);
                mma_bf16(d[cs][ns], ah[cs], bl[ns]);
            }
    }

#pragma unroll
    for (int cs = 0; cs < 2; cs++) {
        int c0r = cbase + cs * 16 + g;
        int c1r = c0r + 8;
        float sc0 = scs[c0r], sh0 = shs[c0r];
        float sc1 = scs[c1r], sh1 = shs[c1r];
#pragma unroll
        for (int ns = 0; ns < 4; ns++) {
            int n = nbase + ns * 8 + 2 * tg;
            const float* dd = d[cs][ns];
            float2 f0 = *(const float2*)&g_f[b * 16384 + c0r * 256 + n];
            float2 f1 = *(const float2*)&g_f[b * 16384 + c1r * 256 + n];
            float2 r0, r1;
            r0.x = fmaxf(fmaf(dd[0], sc0, sh0) + f0.x, 0.f);
            r0.y = fmaxf(fmaf(dd[1], sc0, sh0) + f0.y, 0.f);
            r1.x = fmaxf(fmaf(dd[2], sc1, sh1) + f1.x, 0.f);
            r1.y = fmaxf(fmaf(dd[3], sc1, sh1) + f1.y, 0.f);
            *(float2*)&out[b * 16384 + c0r * 256 + n] = r0;
            *(float2*)&out[b * 16384 + c1r * 256 + n] = r1;
        }
    }
}

// ---------------- launch ----------------
extern "C" void kernel_launch(void* const* d_in, const int* in_sizes, int n_in,
                              void* d_out, int out_size) {
    int base = (in_sizes[2] == 512) ? 2 : 3;

    const float* x          = (const float*)d_in[0];
    const int*   stroke     = (const int*)d_in[1];
    const float* ga_q_w     = (const float*)d_in[base + 0];
    const float* ga_k_w     = (const float*)d_in[base + 1];
    const float* ga_v_w     = (const float*)d_in[base + 2];
    const float* ga_v_b     = (const float*)d_in[base + 3];
    const float* ga_bn_p    = (const float*)d_in[base + 4];
    const float* ga_lb_w    = (const float*)d_in[base + 5];
    const float* ga_lb_bn_p = (const float*)d_in[base + 6];
    const float* sa_q_w     = (const float*)d_in[base + 7];
    const float* sa_k_w     = (const float*)d_in[base + 8];
    const float* sa_v_w     = (const float*)d_in[base + 9];
    const float* sa_v_b     = (const float*)d_in[base + 10];
    const float* sa_bn_p    = (const float*)d_in[base + 11];
    const float* sa_lb_w    = (const float*)d_in[base + 12];
    const float* sa_lb_bn_p = (const float*)d_in[base + 13];
    const float* mlp_w1     = (const float*)d_in[base + 14];
    const float* mlp_bn1_p  = (const float*)d_in[base + 15];
    const float* mlp_w2     = (const float*)d_in[base + 16];
    const float* mlp_bn2_p  = (const float*)d_in[base + 17];

    cudaFuncSetAttribute(attn_kernel, cudaFuncAttributeMaxDynamicSharedMemorySize, ATTN_SMEM_BYTES);

    proj_kernel<<<dim3(64, 16), 128>>>(x, ga_q_w, ga_k_w, ga_v_w, ga_lb_w,
                                       sa_q_w, sa_k_w, sa_v_w, sa_lb_w);
    wsplit_kernel<<<16, 256>>>(mlp_w1, mlp_w2);
    attn_kernel<<<dim3(64, 4), 256, ATTN_SMEM_BYTES>>>(stroke, ga_v_b, sa_v_b,
                                                       ga_bn_p, ga_lb_bn_p,
                                                       sa_bn_p, sa_lb_bn_p);
    mlp1_mma_kernel<<<dim3(16, 64), 128>>>(mlp_bn1_p);
    mlp2_mma_kernel<<<dim3(4, 64), 128>>>(mlp_bn2_p, (float*)d_out);
}